// round 7
// baseline (speedup 1.0000x reference)
#include <cuda_runtime.h>
#include <cstdint>

#define B_  8
#define L_  1024
#define D_  256
#define H_  8
#define HD_ 2048
#define F_  1024
#define ROWS_ (B_*L_)
#define EPS_ 1e-5f

#if defined(__CUDA_ARCH_FEAT_SM103_ALL) || defined(__CUDA_ARCH_FEAT_SM100_ALL)
#define TC_OK 1
#else
#define TC_OK 0
#endif

// --------------------------- scratch (device globals) ------------------------
__device__ float g_Q[(size_t)ROWS_ * HD_];
__device__ float g_K[(size_t)ROWS_ * HD_];
__device__ float g_V[(size_t)ROWS_ * HD_];
__device__ float g_Vt[(size_t)B_ * H_ * D_ * L_];
__device__ float g_S[(size_t)B_ * H_ * L_ * L_];
__device__ float g_O[(size_t)ROWS_ * HD_];
__device__ float g_R1[(size_t)ROWS_ * D_];
__device__ float g_Z1[(size_t)ROWS_ * D_];
__device__ float g_Z1r[(size_t)ROWS_ * D_];
__device__ float g_Hb[(size_t)ROWS_ * F_];
__device__ float g_F[(size_t)ROWS_ * D_];
__device__ float g_L[(size_t)B_ * H_ * L_];
__device__ float g_xr[(size_t)ROWS_ * D_];
__device__ float g_Wqr[(size_t)HD_ * D_];
__device__ float g_Wkr[(size_t)HD_ * D_];
__device__ float g_Wvr[(size_t)HD_ * D_];
__device__ float g_Wur[(size_t)D_ * HD_];
__device__ float g_W1r[(size_t)F_ * D_];
__device__ float g_W2r[(size_t)D_ * F_];

// --------------------------- common helpers ----------------------------------
__device__ __forceinline__ uint32_t f2tf(float f) {
    uint32_t u; asm("cvt.rna.tf32.f32 %0, %1;" : "=r"(u) : "f"(f)); return u;
}
__device__ __forceinline__ float f2tf_f(float f) { return __uint_as_float(f2tf(f)); }

__device__ __forceinline__ void cp16(uint32_t saddr, const void* gptr) {
    asm volatile("cp.async.cg.shared.global [%0], [%1], 16;" :: "r"(saddr), "l"(gptr));
}
__device__ __forceinline__ void cp_commit() { asm volatile("cp.async.commit_group;"); }
__device__ __forceinline__ void cp_wait1()  { asm volatile("cp.async.wait_group 1;"); }
__device__ __forceinline__ void cp_wait0()  { asm volatile("cp.async.wait_group 0;"); }

__device__ __forceinline__ void mma8(float* c, const uint32_t* a, const uint32_t* b) {
    asm volatile(
        "mma.sync.aligned.m16n8k8.row.col.f32.tf32.tf32.f32 "
        "{%0,%1,%2,%3}, {%4,%5,%6,%7}, {%8,%9}, {%0,%1,%2,%3};"
        : "+f"(c[0]), "+f"(c[1]), "+f"(c[2]), "+f"(c[3])
        : "r"(a[0]), "r"(a[1]), "r"(a[2]), "r"(a[3]), "r"(b[0]), "r"(b[1]));
}

#if TC_OK
// --------------------------- tcgen05 helpers (sm_103a pass only) -------------
__device__ __forceinline__ bool elect1() {
    uint32_t p;
    asm volatile("{\n\t.reg .pred p;\n\telect.sync _|p, 0xFFFFFFFF;\n\tselp.b32 %0,1,0,p;\n\t}" : "=r"(p));
    return p != 0;
}
__device__ __forceinline__ void mbar_init(uint32_t a, uint32_t cnt) {
    asm volatile("mbarrier.init.shared.b64 [%0], %1;" :: "r"(a), "r"(cnt) : "memory");
}
__device__ __forceinline__ void mbar_wait(uint32_t a, uint32_t parity) {
    asm volatile(
        "{\n\t.reg .pred P;\n\t"
        "WL%=:\n\t"
        "mbarrier.try_wait.parity.acquire.cta.shared::cta.b64 P, [%0], %1, 0x989680;\n\t"
        "@P bra WD%=;\n\t"
        "bra WL%=;\n\t"
        "WD%=:\n\t}"
        :: "r"(a), "r"(parity) : "memory");
}
__device__ __forceinline__ void fence_pa() {
    asm volatile("fence.proxy.async.shared::cta;" ::: "memory");
}
__device__ __forceinline__ void tc_fence_after() {
    asm volatile("tcgen05.fence::after_thread_sync;" ::: "memory");
}
__device__ __forceinline__ void tcalloc(uint32_t smem_addr, uint32_t ncols) {
    asm volatile("tcgen05.alloc.cta_group::1.sync.aligned.shared::cta.b32 [%0], %1;"
                 :: "r"(smem_addr), "r"(ncols) : "memory");
}
__device__ __forceinline__ void tcdealloc(uint32_t tmem, uint32_t ncols) {
    asm volatile("tcgen05.dealloc.cta_group::1.sync.aligned.b32 %0, %1;" :: "r"(tmem), "r"(ncols));
}
__device__ __forceinline__ void tcrelinquish() {
    asm volatile("tcgen05.relinquish_alloc_permit.cta_group::1.sync.aligned;");
}
__device__ __forceinline__ void tc_commit(uint32_t mbar) {
    asm volatile("tcgen05.commit.cta_group::1.mbarrier::arrive::one.shared::cluster.b64 [%0];"
                 :: "r"(mbar) : "memory");
}
__device__ __forceinline__ void wait_ld() {
    asm volatile("tcgen05.wait::ld.sync.aligned;" ::: "memory");
}
__device__ __forceinline__ void mma_tf32_ss(uint32_t d, uint64_t ad, uint64_t bd,
                                            uint32_t idesc, uint32_t en) {
    asm volatile(
        "{\n\t.reg .pred p;\n\tsetp.ne.u32 p, %4, 0;\n\t"
        "tcgen05.mma.cta_group::1.kind::tf32 [%0], %1, %2, %3, {%5,%5,%5,%5}, p;\n\t}"
        :: "r"(d), "l"(ad), "l"(bd), "r"(idesc), "r"(en), "r"(0u) : "memory");
}
__device__ __forceinline__ void ldtm32(uint32_t* r, uint32_t a) {
    asm volatile(
        "tcgen05.ld.sync.aligned.32x32b.x32.b32 "
        "{%0,%1,%2,%3,%4,%5,%6,%7,%8,%9,%10,%11,%12,%13,%14,%15,"
        "%16,%17,%18,%19,%20,%21,%22,%23,%24,%25,%26,%27,%28,%29,%30,%31}, [%32];"
        : "=r"(r[0]), "=r"(r[1]), "=r"(r[2]), "=r"(r[3]),
          "=r"(r[4]), "=r"(r[5]), "=r"(r[6]), "=r"(r[7]),
          "=r"(r[8]), "=r"(r[9]), "=r"(r[10]), "=r"(r[11]),
          "=r"(r[12]), "=r"(r[13]), "=r"(r[14]), "=r"(r[15]),
          "=r"(r[16]), "=r"(r[17]), "=r"(r[18]), "=r"(r[19]),
          "=r"(r[20]), "=r"(r[21]), "=r"(r[22]), "=r"(r[23]),
          "=r"(r[24]), "=r"(r[25]), "=r"(r[26]), "=r"(r[27]),
          "=r"(r[28]), "=r"(r[29]), "=r"(r[30]), "=r"(r[31])
        : "r"(a));
}
// idesc: dtype=F32(1)@4, atype=TF32(2)@7, btype=TF32(2)@10, N/8@17, M/16@24
static constexpr uint32_t IDESC_TF32 =
    (1u << 4) | (2u << 7) | (2u << 10) | ((256u / 8) << 17) | ((128u / 16) << 24);
static constexpr uint64_t DESC_BASE =
    (uint64_t(2) << 61) | (uint64_t(1) << 46) | (uint64_t(64) << 32) | (uint64_t(1) << 16);
__device__ __forceinline__ uint64_t mk_desc(uint32_t a) {
    return DESC_BASE | ((uint64_t)(a >> 4) & 0x3FFFull);
}
// blocked SW128: rows x 64 tf32 K-chunk; atoms 8r x 128B; atom idx = (q>>3)*(rows/8) + (r>>3)
__device__ __forceinline__ uint32_t tileA_off(int r, int q) {   // 128 rows
    uint32_t byte = (uint32_t)((((q >> 3) * 16 + (r >> 3)) << 10) + ((r & 7) << 7) + ((q & 7) << 4));
    return byte ^ ((byte >> 3) & 0x70);
}
__device__ __forceinline__ uint32_t tileB_off(int r, int q) {   // 256 rows
    uint32_t byte = (uint32_t)((((q >> 3) * 32 + (r >> 3)) << 10) + ((r & 7) << 7) + ((q & 7) << 4));
    return byte ^ ((byte >> 3) & 0x70);
}
#endif // TC_OK

// ============================================================================
// GEMM: C = A @ B^T  (A [M,K] lda, B [N,K] ldb, K-major, tf32-prerounded)
// CTA tile 128x256, K chunks of 64, single-stage smem (96KB), 2 CTAs/SM.
// Epilogue: bias/resid/relu/round; Lsum -> write exp(v*escale) + row sums;
// Ldiv -> scale rows by 1/Ldiv[row].
// ============================================================================
__global__ __launch_bounds__(256, 2)
void gemm_tc(const float* __restrict__ A, const float* __restrict__ Bm,
             float* __restrict__ C, int K, int lda, int ldb, int ldc,
             long long sA1, long long sA2, long long sB1, long long sB2,
             long long sC1, long long sC2,
             const float* __restrict__ bias, const float* __restrict__ resid, int ldres,
             int relu, int round_out, float escale,
             float* __restrict__ Lsum, const float* __restrict__ Ldiv)
{
    extern __shared__ __align__(1024) uint8_t smraw[];

    const int z = blockIdx.z;
    A  += (size_t)(z >> 3) * sA1 + (size_t)(z & 7) * sA2;
    Bm += (size_t)(z >> 3) * sB1 + (size_t)(z & 7) * sB2;
    C  += (size_t)(z >> 3) * sC1 + (size_t)(z & 7) * sC2;

    const int tid = threadIdx.x, wid = tid >> 5, lane = tid & 31;
    const int row0 = blockIdx.y * 128;

#if TC_OK
    const int col0 = blockIdx.x * 256;
    const uint32_t smb = (uint32_t)__cvta_generic_to_shared(smraw);
    const uint32_t bA = smb;             // 32 KB
    const uint32_t bB = smb + 32768u;    // 64 KB
    const uint32_t tptr = smb + 98304u;
    const uint32_t mb0 = smb + 98312u;

    if (wid == 0) tcalloc(tptr, 256);
    if (tid == 0) mbar_init(mb0, 1);
    __syncthreads();
    uint32_t tmem;
    asm volatile("ld.shared.b32 %0, [%1];" : "=r"(tmem) : "r"(tptr));

    const uint64_t ad0 = mk_desc(bA), bd0 = mk_desc(bB);
    const int T = K >> 6;
    int ph = 0;

    for (int t = 0; t < T; ++t) {
        const int k0 = t << 6;
        // stage A (128x64) and B (256x64), SW128 blocked
        {
            const float* Ap = A + (size_t)row0 * lda + k0;
            const float* Bp = Bm + (size_t)col0 * ldb + k0;
#pragma unroll
            for (int i = 0; i < 8; i++) {
                const int s = tid + i * 256, r = s >> 4, q = s & 15;
                cp16(bA + tileA_off(r, q), Ap + (size_t)r * lda + q * 4);
            }
#pragma unroll
            for (int i = 0; i < 16; i++) {
                const int s = tid + i * 256, r = s >> 4, q = s & 15;
                cp16(bB + tileB_off(r, q), Bp + (size_t)r * ldb + q * 4);
            }
        }
        cp_commit(); cp_wait0();
        fence_pa();
        __syncthreads();

        if (wid == 0 && elect1()) {
#pragma unroll
            for (int s = 0; s < 8; ++s) {
                const uint64_t offA = (uint64_t)(((s >> 2) << 10) + ((s & 3) << 1));
                const uint64_t offB = (uint64_t)(((s >> 2) << 11) + ((s & 3) << 1));
                mma_tf32_ss(tmem, ad0 + offA, bd0 + offB, IDESC_TF32, (t > 0 || s > 0) ? 1u : 0u);
            }
            tc_commit(mb0);
        }
        mbar_wait(mb0, ph); ph ^= 1;
    }
    tc_fence_after();
    __syncthreads();

    // epilogue: TMEM -> smem transpose -> coalesced STG (4 warps, 8 col blocks)
    if (wid < 4) {
        float* wsm = (float*)smraw + wid * (32 * 33);
        const int rloc = wid * 32 + lane;
        float rowsum = 0.f;
#pragma unroll 1
        for (int cb = 0; cb < 8; ++cb) {
            uint32_t rg[32];
            ldtm32(rg, tmem + cb * 32);
            wait_ld();
            float vals[32];
#pragma unroll
            for (int j = 0; j < 32; ++j) {
                float v = __uint_as_float(rg[j]);
                if (Lsum) { v = f2tf_f(__expf(v * escale)); rowsum += v; }
                vals[j] = v;
            }
            __syncwarp();
#pragma unroll
            for (int j = 0; j < 32; ++j) wsm[lane * 33 + j] = vals[j];
            __syncwarp();
#pragma unroll 1
            for (int jr = 0; jr < 32; ++jr) {
                const int orow = row0 + wid * 32 + jr;
                const int ocol = col0 + cb * 32 + lane;
                float v = wsm[jr * 33 + lane];
                if (bias)  v += bias[ocol];
                if (resid) v += resid[(size_t)orow * ldres + ocol];
                if (Ldiv)  v *= __frcp_rn(Ldiv[(size_t)z * L_ + orow]);
                if (relu)  v = fmaxf(v, 0.f);
                if (round_out) v = f2tf_f(v);
                C[(size_t)orow * ldc + ocol] = v;
            }
            __syncwarp();
        }
        if (Lsum) atomicAdd(&Lsum[(size_t)z * L_ + row0 + rloc], rowsum);
    }
    __syncthreads();
    if (wid == 0) { tcrelinquish(); tcdealloc(tmem, 256); }

#else  // ----------------- mma.sync fallback (compute_103 pass only) ---------
    constexpr int ASTG = 128 * 36, STG = 2 * ASTG;
    uint32_t* sm = (uint32_t*)smraw;
    const int wm = wid & 3, wn = wid >> 2;
    const int g = lane >> 2, tg = lane & 3;
    const uint32_t smb = (uint32_t)__cvta_generic_to_shared(sm);

    for (int half = 0; half < 2; ++half) {
        const int col0 = blockIdx.x * 256 + half * 128;
        float acc[2][8][4] = {};

        auto stage = [&](int st, int k0) {
            const uint32_t baseA = smb + (uint32_t)(st * STG) * 4u;
            const uint32_t baseB = baseA + (uint32_t)ASTG * 4u;
#pragma unroll
            for (int i = 0; i < 4; i++) {
                const int s = tid + i * 256, r = s >> 3, kq = s & 7;
                cp16(baseA + (uint32_t)(r * 36 + kq * 4) * 4u, A + (size_t)(row0 + r) * lda + k0 + kq * 4);
                cp16(baseB + (uint32_t)(r * 36 + kq * 4) * 4u, Bm + (size_t)(col0 + r) * ldb + k0 + kq * 4);
            }
        };

        const int T = K >> 5;
        stage(0, 0); cp_commit();
        for (int t = 0; t < T; ++t) {
            if (t + 1 < T) { stage((t + 1) & 1, (t + 1) << 5); cp_commit(); cp_wait1(); }
            else           { cp_wait0(); }
            __syncthreads();
            const uint32_t* As = sm + (t & 1) * STG;
            const uint32_t* Bs = As + ASTG;
#pragma unroll
            for (int ks = 0; ks < 32; ks += 8) {
                uint32_t a[2][4], b[8][2];
#pragma unroll
                for (int mf = 0; mf < 2; mf++) {
                    const int m0 = wm * 32 + mf * 16;
                    a[mf][0] = As[(m0 + g) * 36 + ks + tg];
                    a[mf][1] = As[(m0 + 8 + g) * 36 + ks + tg];
                    a[mf][2] = As[(m0 + g) * 36 + ks + 4 + tg];
                    a[mf][3] = As[(m0 + 8 + g) * 36 + ks + 4 + tg];
                }
#pragma unroll
                for (int nf = 0; nf < 8; nf++) {
                    const int n0 = wn * 64 + nf * 8;
                    b[nf][0] = Bs[(n0 + g) * 36 + ks + tg];
                    b[nf][1] = Bs[(n0 + g) * 36 + ks + 4 + tg];
                }
#pragma unroll
                for (int mf = 0; mf < 2; mf++)
#pragma unroll
                    for (int nf = 0; nf < 8; nf++)
                        mma8(acc[mf][nf], a[mf], b[nf]);
            }
            __syncthreads();
        }

        float rowsum[2][2] = {};
#pragma unroll
        for (int mf = 0; mf < 2; mf++)
#pragma unroll
            for (int nf = 0; nf < 8; nf++)
#pragma unroll
                for (int q = 0; q < 4; q++) {
                    const int rr = row0 + wm * 32 + mf * 16 + g + (q >> 1) * 8;
                    const int cc = col0 + wn * 64 + nf * 8 + 2 * tg + (q & 1);
                    float v = acc[mf][nf][q];
                    if (Lsum) { v = f2tf_f(__expf(v * escale)); rowsum[mf][q >> 1] += v; }
                    if (bias)  v += bias[cc];
                    if (resid) v += resid[(size_t)rr * ldres + cc];
                    if (Ldiv)  v *= __frcp_rn(Ldiv[(size_t)z * L_ + rr]);
                    if (relu)  v = fmaxf(v, 0.f);
                    if (round_out) v = f2tf_f(v);
                    C[(size_t)rr * ldc + cc] = v;
                }
        if (Lsum) {
#pragma unroll
            for (int mf = 0; mf < 2; mf++)
#pragma unroll
                for (int qh = 0; qh < 2; qh++) {
                    float s = rowsum[mf][qh];
                    s += __shfl_xor_sync(~0u, s, 1);
                    s += __shfl_xor_sync(~0u, s, 2);
                    if (tg == 0)
                        atomicAdd(&Lsum[(size_t)z * L_ + row0 + wm * 32 + mf * 16 + g + qh * 8], s);
                }
        }
        __syncthreads();
    }
#endif
}

// --------------------------- merged tf32 rounding pass -----------------------
__global__ void cvt_all_kernel(const float4* x, float4* xr,
                               const float4* wq, float4* wqr,
                               const float4* wk, float4* wkr,
                               const float4* wv, float4* wvr,
                               const float4* wu, float4* wur,
                               const float4* w1, float4* w1r,
                               const float4* w2, float4* w2r)
{
    // segment sizes in float4: x 524288, wq/wk/wv/wu 131072 each, w1/w2 65536
    const int total = 524288 + 4 * 131072 + 2 * 65536;   // 1179648
    for (int i = blockIdx.x * blockDim.x + threadIdx.x; i < total; i += gridDim.x * blockDim.x) {
        const float4* in; float4* out; int j = i;
        if (j < 524288) { in = x; out = xr; }
        else if ((j -= 524288) < 131072) { in = wq; out = wqr; }
        else if ((j -= 131072) < 131072) { in = wk; out = wkr; }
        else if ((j -= 131072) < 131072) { in = wv; out = wvr; }
        else if ((j -= 131072) < 131072) { in = wu; out = wur; }
        else if ((j -= 131072) < 65536)  { in = w1; out = w1r; }
        else { j -= 65536; in = w2; out = w2r; }
        float4 v = in[j];
        v.x = f2tf_f(v.x); v.y = f2tf_f(v.y); v.z = f2tf_f(v.z); v.w = f2tf_f(v.w);
        out[j] = v;
    }
}

// --------------------------- V transpose: Vt[z][e][j] = V[b, j, h*256+e] -----
__global__ void transpose_v(const float* __restrict__ V, float* __restrict__ Vt)
{
    __shared__ float t[32][33];
    const int z = blockIdx.z, b = z >> 3, h = z & 7;
    const int j0 = blockIdx.x * 32, e0 = blockIdx.y * 32;
    const int tx = threadIdx.x, ty = threadIdx.y;
#pragma unroll
    for (int k = 0; k < 4; k++)
        t[ty + k * 8][tx] = V[(size_t)(b * L_ + j0 + ty + k * 8) * HD_ + h * D_ + e0 + tx];
    __syncthreads();
#pragma unroll
    for (int k = 0; k < 4; k++)
        Vt[(size_t)z * D_ * L_ + (size_t)(e0 + ty + k * 8) * L_ + j0 + tx] = t[tx][ty + k * 8];
}

// --------------------------- layernorm over d=256 ----------------------------
__global__ void ln_kernel(const float* __restrict__ in, float* __restrict__ out,
                          float* __restrict__ out_r,
                          const float* __restrict__ g, const float* __restrict__ be)
{
    __shared__ float r1[8], r2[8];
    const int row = blockIdx.x, t = threadIdx.x;
    const float v = in[(size_t)row * D_ + t];
    float s = v, q = v * v;
#pragma unroll
    for (int o = 16; o; o >>= 1) {
        s += __shfl_xor_sync(~0u, s, o);
        q += __shfl_xor_sync(~0u, q, o);
    }
    if ((t & 31) == 0) { r1[t >> 5] = s; r2[t >> 5] = q; }
    __syncthreads();
    float S = 0.f, Q = 0.f;
#pragma unroll
    for (int i = 0; i < 8; i++) { S += r1[i]; Q += r2[i]; }
    const float mean = S * (1.f / D_);
    const float var = Q * (1.f / D_) - mean * mean;
    const float y = (v - mean) * rsqrtf(var + EPS_) * g[t] + be[t];
    out[(size_t)row * D_ + t] = y;
    if (out_r) out_r[(size_t)row * D_ + t] = f2tf_f(y);
}

// --------------------------- launch ------------------------------------------
extern "C" void kernel_launch(void* const* d_in, const int* in_sizes, int n_in,
                              void* d_out, int out_size)
{
    const float* x   = (const float*)d_in[0];
    const float* Wq  = (const float*)d_in[1];
    const float* Wk  = (const float*)d_in[2];
    const float* Wv  = (const float*)d_in[3];
    const float* Wu  = (const float*)d_in[4];
    const float* bu  = (const float*)d_in[5];
    const float* W1  = (const float*)d_in[6];
    const float* b1  = (const float*)d_in[7];
    const float* W2  = (const float*)d_in[8];
    const float* b2  = (const float*)d_in[9];
    const float* g1  = (const float*)d_in[10];
    const float* be1 = (const float*)d_in[11];
    const float* g2  = (const float*)d_in[12];
    const float* be2 = (const float*)d_in[13];
    float* out = (float*)d_out;

    float *Qb, *Kb, *Vb, *Vt, *S, *O, *R1, *Z1, *Z1r, *Hb, *F, *Lb;
    float *xr, *Wqr, *Wkr, *Wvr, *Wur, *W1r, *W2r;
    cudaGetSymbolAddress((void**)&Qb, g_Q);
    cudaGetSymbolAddress((void**)&Kb, g_K);
    cudaGetSymbolAddress((void**)&Vb, g_V);
    cudaGetSymbolAddress((void**)&Vt, g_Vt);
    cudaGetSymbolAddress((void**)&S,  g_S);
    cudaGetSymbolAddress((void**)&O,  g_O);
    cudaGetSymbolAddress((void**)&R1, g_R1);
    cudaGetSymbolAddress((void**)&Z1, g_Z1);
    cudaGetSymbolAddress((void**)&Z1r, g_Z1r);
    cudaGetSymbolAddress((void**)&Hb, g_Hb);
    cudaGetSymbolAddress((void**)&F,  g_F);
    cudaGetSymbolAddress((void**)&Lb, g_L);
    cudaGetSymbolAddress((void**)&xr,  g_xr);
    cudaGetSymbolAddress((void**)&Wqr, g_Wqr);
    cudaGetSymbolAddress((void**)&Wkr, g_Wkr);
    cudaGetSymbolAddress((void**)&Wvr, g_Wvr);
    cudaGetSymbolAddress((void**)&Wur, g_Wur);
    cudaGetSymbolAddress((void**)&W1r, g_W1r);
    cudaGetSymbolAddress((void**)&W2r, g_W2r);

    constexpr int SMEM = 98368;   // 96KB staging + tmem ptr + mbar
    cudaFuncSetAttribute(gemm_tc, cudaFuncAttributeMaxDynamicSharedMemorySize, SMEM);

    // merged tf32 rounding of all GEMM inputs
    cvt_all_kernel<<<1184, 256>>>((const float4*)x,  (float4*)xr,
                                  (const float4*)Wq, (float4*)Wqr,
                                  (const float4*)Wk, (float4*)Wkr,
                                  (const float4*)Wv, (float4*)Wvr,
                                  (const float4*)Wu, (float4*)Wur,
                                  (const float4*)W1, (float4*)W1r,
                                  (const float4*)W2, (float4*)W2r);

    const long long LL2 = (long long)L_ * L_;

    // QKV projections: [8192,256] @ [2048,256]^T, tf32-rounded out
    gemm_tc<<<dim3(HD_/256, ROWS_/128, 1), 256, SMEM>>>(xr, Wqr, Qb, D_, D_, D_, HD_,
        0,0,0,0,0,0, nullptr, nullptr, 0, 0, 1, 0.f, nullptr, nullptr);
    gemm_tc<<<dim3(HD_/256, ROWS_/128, 1), 256, SMEM>>>(xr, Wkr, Kb, D_, D_, D_, HD_,
        0,0,0,0,0,0, nullptr, nullptr, 0, 0, 1, 0.f, nullptr, nullptr);
    gemm_tc<<<dim3(HD_/256, ROWS_/128, 1), 256, SMEM>>>(xr, Wvr, Vb, D_, D_, D_, HD_,
        0,0,0,0,0,0, nullptr, nullptr, 0, 0, 1, 0.f, nullptr, nullptr);

    transpose_v<<<dim3(L_/32, D_/32, B_*H_), dim3(32, 8)>>>(Vb, Vt);

    // scores + fused exp & row-sum:  S = exp(Q@K^T / 16), Lb[row] = sum
    cudaMemsetAsync(Lb, 0, (size_t)B_ * H_ * L_ * sizeof(float));
    gemm_tc<<<dim3(L_/256, L_/128, B_*H_), 256, SMEM>>>(Qb, Kb, S, D_, HD_, HD_, L_,
        (long long)L_*HD_, D_, (long long)L_*HD_, D_, 8*LL2, LL2,
        nullptr, nullptr, 0, 0, 0, 0.0625f, Lb, nullptr);

    // PV: O = (S @ Vt^T) / l   (rounded)
    gemm_tc<<<dim3(D_/256, L_/128, B_*H_), 256, SMEM>>>(S, Vt, O, L_, L_, L_, HD_,
        8*LL2, LL2, 8LL*D_*L_, (long long)D_*L_, (long long)L_*HD_, D_,
        nullptr, nullptr, 0, 0, 1, 0.f, nullptr, Lb);

    // output projection + bias + residual(x)
    gemm_tc<<<dim3(D_/256, ROWS_/128, 1), 256, SMEM>>>(O, Wur, R1, HD_, HD_, HD_, D_,
        0,0,0,0,0,0, bu, x, D_, 0, 0, 0.f, nullptr, nullptr);
    ln_kernel<<<ROWS_, 256>>>(R1, Z1, Z1r, g1, be1);

    // FFN
    gemm_tc<<<dim3(F_/256, ROWS_/128, 1), 256, SMEM>>>(Z1r, W1r, Hb, D_, D_, D_, F_,
        0,0,0,0,0,0, b1, nullptr, 0, 1, 1, 0.f, nullptr, nullptr);
    gemm_tc<<<dim3(D_/256, ROWS_/128, 1), 256, SMEM>>>(Hb, W2r, F, F_, F_, F_, D_,
        0,0,0,0,0,0, b2, Z1, D_, 0, 0, 0.f, nullptr, nullptr);
    ln_kernel<<<ROWS_, 256>>>(F, out, nullptr, g2, be2);
}

// round 8
// speedup vs baseline: 1.4300x; 1.4300x over previous
#include <cuda_runtime.h>
#include <cstdint>

#define B_  8
#define L_  1024
#define D_  256
#define H_  8
#define HD_ 2048
#define F_  1024
#define ROWS_ (B_*L_)
#define EPS_ 1e-5f

#if defined(__CUDA_ARCH_FEAT_SM103_ALL) || defined(__CUDA_ARCH_FEAT_SM100_ALL)
#define TC_OK 1
#else
#define TC_OK 0
#endif

// --------------------------- scratch (device globals) ------------------------
__device__ float g_Q[(size_t)ROWS_ * HD_];
__device__ float g_K[(size_t)ROWS_ * HD_];
__device__ float g_V[(size_t)ROWS_ * HD_];
__device__ float g_Vt[(size_t)B_ * H_ * D_ * L_];
__device__ float g_S[(size_t)B_ * H_ * L_ * L_];
__device__ float g_O[(size_t)ROWS_ * HD_];
__device__ float g_R1[(size_t)ROWS_ * D_];
__device__ float g_Z1[(size_t)ROWS_ * D_];
__device__ float g_Z1r[(size_t)ROWS_ * D_];
__device__ float g_Hb[(size_t)ROWS_ * F_];
__device__ float g_F[(size_t)ROWS_ * D_];
__device__ float g_L[(size_t)B_ * H_ * L_];
__device__ float g_xr[(size_t)ROWS_ * D_];
__device__ float g_Wqr[(size_t)HD_ * D_];
__device__ float g_Wkr[(size_t)HD_ * D_];
__device__ float g_Wvr[(size_t)HD_ * D_];
__device__ float g_Wur[(size_t)D_ * HD_];
__device__ float g_W1r[(size_t)F_ * D_];
__device__ float g_W2r[(size_t)D_ * F_];

// --------------------------- common helpers ----------------------------------
__device__ __forceinline__ uint32_t f2tf(float f) {
    uint32_t u; asm("cvt.rna.tf32.f32 %0, %1;" : "=r"(u) : "f"(f)); return u;
}
__device__ __forceinline__ float f2tf_f(float f) { return __uint_as_float(f2tf(f)); }

__device__ __forceinline__ void cp16(uint32_t saddr, const void* gptr) {
    asm volatile("cp.async.cg.shared.global [%0], [%1], 16;" :: "r"(saddr), "l"(gptr));
}
__device__ __forceinline__ void cp_commit() { asm volatile("cp.async.commit_group;"); }
__device__ __forceinline__ void cp_wait1()  { asm volatile("cp.async.wait_group 1;"); }
__device__ __forceinline__ void cp_wait0()  { asm volatile("cp.async.wait_group 0;"); }

__device__ __forceinline__ void mma8(float* c, const uint32_t* a, const uint32_t* b) {
    asm volatile(
        "mma.sync.aligned.m16n8k8.row.col.f32.tf32.tf32.f32 "
        "{%0,%1,%2,%3}, {%4,%5,%6,%7}, {%8,%9}, {%0,%1,%2,%3};"
        : "+f"(c[0]), "+f"(c[1]), "+f"(c[2]), "+f"(c[3])
        : "r"(a[0]), "r"(a[1]), "r"(a[2]), "r"(a[3]), "r"(b[0]), "r"(b[1]));
}

__device__ __forceinline__ uint32_t swz(uint32_t b) { return b ^ ((b >> 3) & 0x70); }

#if TC_OK
// --------------------------- tcgen05 helpers (sm_103a pass only) -------------
__device__ __forceinline__ bool elect1() {
    uint32_t p;
    asm volatile("{\n\t.reg .pred p;\n\telect.sync _|p, 0xFFFFFFFF;\n\tselp.b32 %0,1,0,p;\n\t}" : "=r"(p));
    return p != 0;
}
__device__ __forceinline__ void mbar_init(uint32_t a, uint32_t cnt) {
    asm volatile("mbarrier.init.shared.b64 [%0], %1;" :: "r"(a), "r"(cnt) : "memory");
}
__device__ __forceinline__ void mbar_wait(uint32_t a, uint32_t parity) {
    asm volatile(
        "{\n\t.reg .pred P;\n\t"
        "WL%=:\n\t"
        "mbarrier.try_wait.parity.acquire.cta.shared::cta.b64 P, [%0], %1, 0x989680;\n\t"
        "@P bra WD%=;\n\t"
        "bra WL%=;\n\t"
        "WD%=:\n\t}"
        :: "r"(a), "r"(parity) : "memory");
}
__device__ __forceinline__ void cp_arrive_noinc(uint32_t mbar) {
    asm volatile("cp.async.mbarrier.arrive.noinc.shared::cta.b64 [%0];" :: "r"(mbar) : "memory");
}
__device__ __forceinline__ void tc_fence_after() {
    asm volatile("tcgen05.fence::after_thread_sync;" ::: "memory");
}
__device__ __forceinline__ void tcalloc(uint32_t smem_addr, uint32_t ncols) {
    asm volatile("tcgen05.alloc.cta_group::1.sync.aligned.shared::cta.b32 [%0], %1;"
                 :: "r"(smem_addr), "r"(ncols) : "memory");
}
__device__ __forceinline__ void tcdealloc(uint32_t tmem, uint32_t ncols) {
    asm volatile("tcgen05.dealloc.cta_group::1.sync.aligned.b32 %0, %1;" :: "r"(tmem), "r"(ncols));
}
__device__ __forceinline__ void tcrelinquish() {
    asm volatile("tcgen05.relinquish_alloc_permit.cta_group::1.sync.aligned;");
}
__device__ __forceinline__ void tc_commit(uint32_t mbar) {
    asm volatile("tcgen05.commit.cta_group::1.mbarrier::arrive::one.shared::cluster.b64 [%0];"
                 :: "r"(mbar) : "memory");
}
__device__ __forceinline__ void wait_ld() {
    asm volatile("tcgen05.wait::ld.sync.aligned;" ::: "memory");
}
__device__ __forceinline__ void mma_tf32_ss(uint32_t d, uint64_t ad, uint64_t bd,
                                            uint32_t idesc, uint32_t en) {
    asm volatile(
        "{\n\t.reg .pred p;\n\tsetp.ne.u32 p, %4, 0;\n\t"
        "tcgen05.mma.cta_group::1.kind::tf32 [%0], %1, %2, %3, {%5,%5,%5,%5}, p;\n\t}"
        :: "r"(d), "l"(ad), "l"(bd), "r"(idesc), "r"(en), "r"(0u) : "memory");
}
__device__ __forceinline__ void ldtm32(uint32_t* r, uint32_t a) {
    asm volatile(
        "tcgen05.ld.sync.aligned.32x32b.x32.b32 "
        "{%0,%1,%2,%3,%4,%5,%6,%7,%8,%9,%10,%11,%12,%13,%14,%15,"
        "%16,%17,%18,%19,%20,%21,%22,%23,%24,%25,%26,%27,%28,%29,%30,%31}, [%32];"
        : "=r"(r[0]), "=r"(r[1]), "=r"(r[2]), "=r"(r[3]),
          "=r"(r[4]), "=r"(r[5]), "=r"(r[6]), "=r"(r[7]),
          "=r"(r[8]), "=r"(r[9]), "=r"(r[10]), "=r"(r[11]),
          "=r"(r[12]), "=r"(r[13]), "=r"(r[14]), "=r"(r[15]),
          "=r"(r[16]), "=r"(r[17]), "=r"(r[18]), "=r"(r[19]),
          "=r"(r[20]), "=r"(r[21]), "=r"(r[22]), "=r"(r[23]),
          "=r"(r[24]), "=r"(r[25]), "=r"(r[26]), "=r"(r[27]),
          "=r"(r[28]), "=r"(r[29]), "=r"(r[30]), "=r"(r[31])
        : "r"(a));
}
static constexpr uint64_t DESC_BASE =
    (uint64_t(2) << 61) | (uint64_t(1) << 46) | (uint64_t(64) << 32) | (uint64_t(1) << 16);
__device__ __forceinline__ uint64_t mk_desc(uint32_t a) {
    return DESC_BASE | ((uint64_t)(a >> 4) & 0x3FFFull);
}
#endif // TC_OK

// ============================================================================
// GEMM: C = A @ B^T  (A [M,K] lda, B [N,K] ldb, K-major, tf32-prerounded)
// CTA tile (MH*128) x NT, KC=32, 3-stage mbarrier pipeline, warp-7 MMA issue.
// Epilogue: bias/resid/relu/round; Lsum -> write exp(v*escale) + row sums;
// Ldiv -> scale rows by 1/Ldiv[row].
// ============================================================================
template<int MH, int NT>
__global__ __launch_bounds__(256)
void gemm_tc(const float* __restrict__ A, const float* __restrict__ Bm,
             float* __restrict__ C, int K, int lda, int ldb, int ldc,
             long long sA1, long long sA2, long long sB1, long long sB2,
             long long sC1, long long sC2,
             const float* __restrict__ bias, const float* __restrict__ resid, int ldres,
             int relu, int round_out, float escale,
             float* __restrict__ Lsum, const float* __restrict__ Ldiv)
{
    extern __shared__ __align__(1024) uint8_t smraw[];

    const int z = blockIdx.z;
    A  += (size_t)(z >> 3) * sA1 + (size_t)(z & 7) * sA2;
    Bm += (size_t)(z >> 3) * sB1 + (size_t)(z & 7) * sB2;
    C  += (size_t)(z >> 3) * sC1 + (size_t)(z & 7) * sC2;

    const int tid = threadIdx.x, wid = tid >> 5, lane = tid & 31;
    const int row0 = blockIdx.y * (MH * 128);
    const int col0 = blockIdx.x * NT;

#if TC_OK
    constexpr int ABYTES = MH * 16384;
    constexpr int BBYTES = (NT / 128) * 16384;
    constexpr int STG = ABYTES + BBYTES;
    constexpr int CTRL = 3 * STG;
    constexpr uint32_t IDESC =
        (1u << 4) | (2u << 7) | (2u << 10) | ((uint32_t)(NT / 8) << 17) | (8u << 24);

    const uint32_t smb = (uint32_t)__cvta_generic_to_shared(smraw);
    const uint32_t tptr = smb + CTRL;
    const uint32_t mbF = smb + CTRL + 8;     // full[0..2]
    const uint32_t mbE = smb + CTRL + 32;    // empty[0..2]
    const uint32_t mbD = smb + CTRL + 56;    // done

    if (wid == 0) tcalloc(tptr, MH * NT);
    if (tid == 0) {
        for (int s = 0; s < 3; ++s) { mbar_init(mbF + 8 * s, 224); mbar_init(mbE + 8 * s, 1); }
        mbar_init(mbD, 1);
    }
    __syncthreads();
    uint32_t tmem;
    asm volatile("ld.shared.b32 %0, [%1];" : "=r"(tmem) : "r"(tptr));

    const int T = K >> 5;

    if (wid < 7) {
        // producers
        int eph[3] = {1, 1, 1};
        int s = 0;
        for (int c = 0; c < T; ++c) {
            mbar_wait(mbE + 8 * s, eph[s]); eph[s] ^= 1;
            const uint32_t bA = smb + s * STG, bB = bA + ABYTES;
            const int k0 = c << 5;
            const float* Ap = A + (size_t)row0 * lda + k0;
            const float* Bp = Bm + (size_t)col0 * ldb + k0;
            constexpr int TOT = (MH * 128 + NT) * 8;
            for (int i = tid; i < TOT; i += 224) {
                const int r = i >> 3, q = i & 7;
                if (r < MH * 128)
                    cp16(bA + swz((uint32_t)(r * 128 + q * 16)), Ap + (size_t)r * lda + q * 4);
                else {
                    const int rb = r - MH * 128;
                    cp16(bB + swz((uint32_t)(rb * 128 + q * 16)), Bp + (size_t)rb * ldb + q * 4);
                }
            }
            cp_arrive_noinc(mbF + 8 * s);
            if (++s == 3) s = 0;
        }
    } else if (elect1()) {
        // MMA issuer
        int fph[3] = {0, 0, 0};
        int s = 0;
        for (int c = 0; c < T; ++c) {
            mbar_wait(mbF + 8 * s, fph[s]); fph[s] ^= 1;
            const uint32_t bA = smb + s * STG, bB = bA + ABYTES;
            const uint64_t bd = mk_desc(bB);
#pragma unroll
            for (int m = 0; m < MH; ++m) {
                const uint64_t ad = mk_desc(bA + m * 16384);
#pragma unroll
                for (int k8 = 0; k8 < 4; ++k8)
                    mma_tf32_ss(tmem + m * NT, ad + 2 * k8, bd + 2 * k8, IDESC,
                                (c > 0 || k8 > 0) ? 1u : 0u);
            }
            tc_commit(mbE + 8 * s);
            if (++s == 3) s = 0;
        }
        tc_commit(mbD);
    }

    mbar_wait(mbD, 0);
    tc_fence_after();
    __syncthreads();

    // epilogue: TMEM -> smem transpose -> coalesced STG
    const int half = wid >> 2, sw = wid & 3;
    if (half < MH) {
        float* wsm = (float*)smraw + wid * (32 * 33);
        const int rloc = half * 128 + sw * 32 + lane;
        float rowsum = 0.f;
#pragma unroll 1
        for (int cb = 0; cb < NT / 32; ++cb) {
            uint32_t rg[32];
            ldtm32(rg, tmem + half * NT + cb * 32);
            wait_ld();
            float vals[32];
#pragma unroll
            for (int j = 0; j < 32; ++j) {
                float v = __uint_as_float(rg[j]);
                if (Lsum) { v = f2tf_f(__expf(v * escale)); rowsum += v; }
                vals[j] = v;
            }
            __syncwarp();
#pragma unroll
            for (int j = 0; j < 32; ++j) wsm[lane * 33 + j] = vals[j];
            __syncwarp();
#pragma unroll 1
            for (int jr = 0; jr < 32; ++jr) {
                const int orow = row0 + half * 128 + sw * 32 + jr;
                const int ocol = col0 + cb * 32 + lane;
                float v = wsm[jr * 33 + lane];
                if (bias)  v += bias[ocol];
                if (resid) v += resid[(size_t)orow * ldres + ocol];
                if (Ldiv)  v *= __frcp_rn(Ldiv[(size_t)z * L_ + orow]);
                if (relu)  v = fmaxf(v, 0.f);
                if (round_out) v = f2tf_f(v);
                C[(size_t)orow * ldc + ocol] = v;
            }
            __syncwarp();
        }
        if (Lsum) atomicAdd(&Lsum[(size_t)z * L_ + row0 + rloc], rowsum);
    }
    __syncthreads();
    if (wid == 0) { tcrelinquish(); tcdealloc(tmem, MH * NT); }

#else  // ----------------- mma.sync fallback (compute_103 pass only) ---------
    constexpr int ASTG = 128 * 36, STG2 = 2 * ASTG;
    uint32_t* sm = (uint32_t*)smraw;
    const int wm = wid & 3, wn = wid >> 2;
    const int g = lane >> 2, tg = lane & 3;
    const uint32_t smb = (uint32_t)__cvta_generic_to_shared(sm);

    for (int mh = 0; mh < MH; ++mh)
    for (int nh = 0; nh < NT / 128; ++nh) {
        const int r0 = row0 + mh * 128, c0 = col0 + nh * 128;
        float acc[2][8][4] = {};

        auto stage = [&](int st, int k0) {
            const uint32_t baseA = smb + (uint32_t)(st * STG2) * 4u;
            const uint32_t baseB = baseA + (uint32_t)ASTG * 4u;
#pragma unroll
            for (int i = 0; i < 4; i++) {
                const int s = tid + i * 256, r = s >> 3, kq = s & 7;
                cp16(baseA + (uint32_t)(r * 36 + kq * 4) * 4u, A + (size_t)(r0 + r) * lda + k0 + kq * 4);
                cp16(baseB + (uint32_t)(r * 36 + kq * 4) * 4u, Bm + (size_t)(c0 + r) * ldb + k0 + kq * 4);
            }
        };

        const int T = K >> 5;
        stage(0, 0); cp_commit();
        for (int t = 0; t < T; ++t) {
            if (t + 1 < T) { stage((t + 1) & 1, (t + 1) << 5); cp_commit(); cp_wait1(); }
            else           { cp_wait0(); }
            __syncthreads();
            const uint32_t* As = sm + (t & 1) * STG2;
            const uint32_t* Bs = As + ASTG;
#pragma unroll
            for (int ks = 0; ks < 32; ks += 8) {
                uint32_t a[2][4], b[8][2];
#pragma unroll
                for (int mf = 0; mf < 2; mf++) {
                    const int m0 = wm * 32 + mf * 16;
                    a[mf][0] = As[(m0 + g) * 36 + ks + tg];
                    a[mf][1] = As[(m0 + 8 + g) * 36 + ks + tg];
                    a[mf][2] = As[(m0 + g) * 36 + ks + 4 + tg];
                    a[mf][3] = As[(m0 + 8 + g) * 36 + ks + 4 + tg];
                }
#pragma unroll
                for (int nf = 0; nf < 8; nf++) {
                    const int n0 = wn * 64 + nf * 8;
                    b[nf][0] = Bs[(n0 + g) * 36 + ks + tg];
                    b[nf][1] = Bs[(n0 + g) * 36 + ks + 4 + tg];
                }
#pragma unroll
                for (int mf = 0; mf < 2; mf++)
#pragma unroll
                    for (int nf = 0; nf < 8; nf++)
                        mma8(acc[mf][nf], a[mf], b[nf]);
            }
            __syncthreads();
        }

        float rowsum[2][2] = {};
#pragma unroll
        for (int mf = 0; mf < 2; mf++)
#pragma unroll
            for (int nf = 0; nf < 8; nf++)
#pragma unroll
                for (int q = 0; q < 4; q++) {
                    const int rr = r0 + wm * 32 + mf * 16 + g + (q >> 1) * 8;
                    const int cc = c0 + wn * 64 + nf * 8 + 2 * tg + (q & 1);
                    float v = acc[mf][nf][q];
                    if (Lsum) { v = f2tf_f(__expf(v * escale)); rowsum[mf][q >> 1] += v; }
                    if (bias)  v += bias[cc];
                    if (resid) v += resid[(size_t)rr * ldres + cc];
                    if (Ldiv)  v *= __frcp_rn(Ldiv[(size_t)z * L_ + rr]);
                    if (relu)  v = fmaxf(v, 0.f);
                    if (round_out) v = f2tf_f(v);
                    C[(size_t)rr * ldc + cc] = v;
                }
        if (Lsum) {
#pragma unroll
            for (int mf = 0; mf < 2; mf++)
#pragma unroll
                for (int qh = 0; qh < 2; qh++) {
                    float s = rowsum[mf][qh];
                    s += __shfl_xor_sync(~0u, s, 1);
                    s += __shfl_xor_sync(~0u, s, 2);
                    if (tg == 0)
                        atomicAdd(&Lsum[(size_t)z * L_ + r0 + wm * 32 + mf * 16 + g + qh * 8], s);
                }
        }
        __syncthreads();
    }
#endif
}

// --------------------------- merged tf32 rounding pass -----------------------
__global__ void cvt_all_kernel(const float4* x, float4* xr,
                               const float4* wq, float4* wqr,
                               const float4* wk, float4* wkr,
                               const float4* wv, float4* wvr,
                               const float4* wu, float4* wur,
                               const float4* w1, float4* w1r,
                               const float4* w2, float4* w2r)
{
    const int total = 524288 + 4 * 131072 + 2 * 65536;   // 1179648 float4
    for (int i = blockIdx.x * blockDim.x + threadIdx.x; i < total; i += gridDim.x * blockDim.x) {
        const float4* in; float4* out; int j = i;
        if (j < 524288) { in = x; out = xr; }
        else if ((j -= 524288) < 131072) { in = wq; out = wqr; }
        else if ((j -= 131072) < 131072) { in = wk; out = wkr; }
        else if ((j -= 131072) < 131072) { in = wv; out = wvr; }
        else if ((j -= 131072) < 131072) { in = wu; out = wur; }
        else if ((j -= 131072) < 65536)  { in = w1; out = w1r; }
        else { j -= 65536; in = w2; out = w2r; }
        float4 v = in[j];
        v.x = f2tf_f(v.x); v.y = f2tf_f(v.y); v.z = f2tf_f(v.z); v.w = f2tf_f(v.w);
        out[j] = v;
    }
}

// --------------------------- V transpose: Vt[z][e][j] = V[b, j, h*256+e] -----
__global__ void transpose_v(const float* __restrict__ V, float* __restrict__ Vt)
{
    __shared__ float t[32][33];
    const int z = blockIdx.z, b = z >> 3, h = z & 7;
    const int j0 = blockIdx.x * 32, e0 = blockIdx.y * 32;
    const int tx = threadIdx.x, ty = threadIdx.y;
#pragma unroll
    for (int k = 0; k < 4; k++)
        t[ty + k * 8][tx] = V[(size_t)(b * L_ + j0 + ty + k * 8) * HD_ + h * D_ + e0 + tx];
    __syncthreads();
#pragma unroll
    for (int k = 0; k < 4; k++)
        Vt[(size_t)z * D_ * L_ + (size_t)(e0 + ty + k * 8) * L_ + j0 + tx] = t[tx][ty + k * 8];
}

// --------------------------- layernorm over d=256 ----------------------------
__global__ void ln_kernel(const float* __restrict__ in, float* __restrict__ out,
                          float* __restrict__ out_r,
                          const float* __restrict__ g, const float* __restrict__ be)
{
    __shared__ float r1[8], r2[8];
    const int row = blockIdx.x, t = threadIdx.x;
    const float v = in[(size_t)row * D_ + t];
    float s = v, q = v * v;
#pragma unroll
    for (int o = 16; o; o >>= 1) {
        s += __shfl_xor_sync(~0u, s, o);
        q += __shfl_xor_sync(~0u, q, o);
    }
    if ((t & 31) == 0) { r1[t >> 5] = s; r2[t >> 5] = q; }
    __syncthreads();
    float S = 0.f, Q = 0.f;
#pragma unroll
    for (int i = 0; i < 8; i++) { S += r1[i]; Q += r2[i]; }
    const float mean = S * (1.f / D_);
    const float var = Q * (1.f / D_) - mean * mean;
    const float y = (v - mean) * rsqrtf(var + EPS_) * g[t] + be[t];
    out[(size_t)row * D_ + t] = y;
    if (out_r) out_r[(size_t)row * D_ + t] = f2tf_f(y);
}

// --------------------------- launch ------------------------------------------
extern "C" void kernel_launch(void* const* d_in, const int* in_sizes, int n_in,
                              void* d_out, int out_size)
{
    const float* x   = (const float*)d_in[0];
    const float* Wq  = (const float*)d_in[1];
    const float* Wk  = (const float*)d_in[2];
    const float* Wv  = (const float*)d_in[3];
    const float* Wu  = (const float*)d_in[4];
    const float* bu  = (const float*)d_in[5];
    const float* W1  = (const float*)d_in[6];
    const float* b1  = (const float*)d_in[7];
    const float* W2  = (const float*)d_in[8];
    const float* b2  = (const float*)d_in[9];
    const float* g1  = (const float*)d_in[10];
    const float* be1 = (const float*)d_in[11];
    const float* g2  = (const float*)d_in[12];
    const float* be2 = (const float*)d_in[13];
    float* out = (float*)d_out;

    float *Qb, *Kb, *Vb, *Vt, *S, *O, *R1, *Z1, *Z1r, *Hb, *F, *Lb;
    float *xr, *Wqr, *Wkr, *Wvr, *Wur, *W1r, *W2r;
    cudaGetSymbolAddress((void**)&Qb, g_Q);
    cudaGetSymbolAddress((void**)&Kb, g_K);
    cudaGetSymbolAddress((void**)&Vb, g_V);
    cudaGetSymbolAddress((void**)&Vt, g_Vt);
    cudaGetSymbolAddress((void**)&S,  g_S);
    cudaGetSymbolAddress((void**)&O,  g_O);
    cudaGetSymbolAddress((void**)&R1, g_R1);
    cudaGetSymbolAddress((void**)&Z1, g_Z1);
    cudaGetSymbolAddress((void**)&Z1r, g_Z1r);
    cudaGetSymbolAddress((void**)&Hb, g_Hb);
    cudaGetSymbolAddress((void**)&F,  g_F);
    cudaGetSymbolAddress((void**)&Lb, g_L);
    cudaGetSymbolAddress((void**)&xr,  g_xr);
    cudaGetSymbolAddress((void**)&Wqr, g_Wqr);
    cudaGetSymbolAddress((void**)&Wkr, g_Wkr);
    cudaGetSymbolAddress((void**)&Wvr, g_Wvr);
    cudaGetSymbolAddress((void**)&Wur, g_Wur);
    cudaGetSymbolAddress((void**)&W1r, g_W1r);
    cudaGetSymbolAddress((void**)&W2r, g_W2r);

    constexpr int SMEM22 = 3 * 65536 + 64;   // <2,256>: 196672
    constexpr int SMEM12 = 3 * 49152 + 64;   // <1,256>: 147520
    cudaFuncSetAttribute(gemm_tc<2,256>, cudaFuncAttributeMaxDynamicSharedMemorySize, SMEM22);
    cudaFuncSetAttribute(gemm_tc<1,256>, cudaFuncAttributeMaxDynamicSharedMemorySize, SMEM12);

    // merged tf32 rounding of all GEMM inputs
    cvt_all_kernel<<<1184, 256>>>((const float4*)x,  (float4*)xr,
                                  (const float4*)Wq, (float4*)Wqr,
                                  (const float4*)Wk, (float4*)Wkr,
                                  (const float4*)Wv, (float4*)Wvr,
                                  (const float4*)Wu, (float4*)Wur,
                                  (const float4*)W1, (float4*)W1r,
                                  (const float4*)W2, (float4*)W2r);

    const long long LL2 = (long long)L_ * L_;

    // QKV projections: [8192,256] @ [2048,256]^T, tf32-rounded out
    gemm_tc<2,256><<<dim3(HD_/256, ROWS_/256, 1), 256, SMEM22>>>(xr, Wqr, Qb, D_, D_, D_, HD_,
        0,0,0,0,0,0, nullptr, nullptr, 0, 0, 1, 0.f, nullptr, nullptr);
    gemm_tc<2,256><<<dim3(HD_/256, ROWS_/256, 1), 256, SMEM22>>>(xr, Wkr, Kb, D_, D_, D_, HD_,
        0,0,0,0,0,0, nullptr, nullptr, 0, 0, 1, 0.f, nullptr, nullptr);
    gemm_tc<2,256><<<dim3(HD_/256, ROWS_/256, 1), 256, SMEM22>>>(xr, Wvr, Vb, D_, D_, D_, HD_,
        0,0,0,0,0,0, nullptr, nullptr, 0, 0, 1, 0.f, nullptr, nullptr);

    transpose_v<<<dim3(L_/32, D_/32, B_*H_), dim3(32, 8)>>>(Vb, Vt);

    // scores + fused exp & row-sum:  S = exp(Q@K^T / 16), Lb[row] = sum
    cudaMemsetAsync(Lb, 0, (size_t)B_ * H_ * L_ * sizeof(float));
    gemm_tc<2,256><<<dim3(L_/256, L_/256, B_*H_), 256, SMEM22>>>(Qb, Kb, S, D_, HD_, HD_, L_,
        (long long)L_*HD_, D_, (long long)L_*HD_, D_, 8*LL2, LL2,
        nullptr, nullptr, 0, 0, 0, 0.0625f, Lb, nullptr);

    // PV: O = (S @ Vt^T) / l   (rounded)
    gemm_tc<2,256><<<dim3(D_/256, L_/256, B_*H_), 256, SMEM22>>>(S, Vt, O, L_, L_, L_, HD_,
        8*LL2, LL2, 8LL*D_*L_, (long long)D_*L_, (long long)L_*HD_, D_,
        nullptr, nullptr, 0, 0, 1, 0.f, nullptr, Lb);

    // output projection + bias + residual(x)
    gemm_tc<1,256><<<dim3(D_/256, ROWS_/128, 1), 256, SMEM12>>>(O, Wur, R1, HD_, HD_, HD_, D_,
        0,0,0,0,0,0, bu, x, D_, 0, 0, 0.f, nullptr, nullptr);
    ln_kernel<<<ROWS_, 256>>>(R1, Z1, Z1r, g1, be1);

    // FFN
    gemm_tc<2,256><<<dim3(F_/256, ROWS_/256, 1), 256, SMEM22>>>(Z1r, W1r, Hb, D_, D_, D_, F_,
        0,0,0,0,0,0, b1, nullptr, 0, 1, 1, 0.f, nullptr, nullptr);
    gemm_tc<1,256><<<dim3(D_/256, ROWS_/128, 1), 256, SMEM12>>>(Hb, W2r, F, F_, F_, F_, D_,
        0,0,0,0,0,0, b2, Z1, D_, 0, 0, 0.f, nullptr, nullptr);
    ln_kernel<<<ROWS_, 256>>>(F, out, nullptr, g2, be2);
}